// round 15
// baseline (speedup 1.0000x reference)
#include <cuda_runtime.h>
#include <cuda_fp16.h>
#include <cstdint>

#define D_MODEL   1024
#define NUM_HEADS 16
#define D_HEAD    64
#define BATCH     4
#define SEQ       2048
#define MTOT      (BATCH * SEQ)   // 8192
#define QKV_EL    (BATCH * NUM_HEADS * SEQ * D_HEAD)   // 8388608

// ---------------- scratch (device globals: allocation-guard safe) ----------
__device__ __half g_xh[MTOT * D_MODEL];                // x single fp16
__device__ __half g_wh[4][D_MODEL * D_MODEL];          // weights single fp16
__device__ __half g_qh[QKV_EL];                        // [b,h,s,d] single
__device__ __half g_kh[QKV_EL];                        // [b,h,s,d] single
__device__ __half g_vth[QKV_EL];                       // [b,h,d,s] single
__device__ __half g_ch[MTOT * D_MODEL];                // ctx single

// ---------------- helpers ----------------------------------------------------
__device__ __forceinline__ unsigned pk(__half a, __half b) {
    return (unsigned)__half_as_ushort(a) | ((unsigned)__half_as_ushort(b) << 16);
}
__device__ __forceinline__ void round_store4(float4 v, __half* hp) {
    *(uint2*)hp = make_uint2(pk(__float2half_rn(v.x), __float2half_rn(v.y)),
                             pk(__float2half_rn(v.z), __float2half_rn(v.w)));
}
// fp32-accumulator mma (fp16 inputs)
__device__ __forceinline__ void mmaF(float* c, const unsigned* a, unsigned b0, unsigned b1) {
    asm volatile(
        "mma.sync.aligned.m16n8k16.row.col.f32.f16.f16.f32 "
        "{%0,%1,%2,%3}, {%4,%5,%6,%7}, {%8,%9}, {%0,%1,%2,%3};"
        : "+f"(c[0]), "+f"(c[1]), "+f"(c[2]), "+f"(c[3])
        : "r"(a[0]), "r"(a[1]), "r"(a[2]), "r"(a[3]), "r"(b0), "r"(b1));
}
__device__ __forceinline__ void ldsm4(unsigned r[4], const __half* p) {
    unsigned a = (unsigned)__cvta_generic_to_shared(p);
    asm volatile("ldmatrix.sync.aligned.m8n8.x4.shared.b16 {%0,%1,%2,%3}, [%4];"
                 : "=r"(r[0]), "=r"(r[1]), "=r"(r[2]), "=r"(r[3]) : "r"(a));
}
__device__ __forceinline__ void cp16(__half* s, const __half* g) {
    unsigned sa = (unsigned)__cvta_generic_to_shared(s);
    asm volatile("cp.async.cg.shared.global [%0], [%1], 16;" :: "r"(sa), "l"(g));
}
#define CP_COMMIT() asm volatile("cp.async.commit_group;")
#define CP_WAIT0()  asm volatile("cp.async.wait_group 0;")
#define CP_WAIT1()  asm volatile("cp.async.wait_group 1;")

// fast exp2 on the FMA pipe (MUFU-free)
__device__ __forceinline__ float exp2_fast(float y) {
    y = fmaxf(y, -120.f);
    float z = y + 12582912.f;
    int   e = __float_as_int(z);
    float f = y - (z - 12582912.f);
    float p = 1.f + f * (0.6931471805599453f + f * (0.2402265069591007f +
              f * (0.0555041086648216f + f * (0.0096181291076285f +
              f * 0.0013333558146429f))));
    return __int_as_float(__float_as_int(p) + (e << 23));
}
#define SCALE_LOG2E 0.18033688011112042f   // 0.125 * log2(e)

// ---------------- one-shot fp16 rounding of x + weights ----------------------
__global__ __launch_bounds__(256) void split_all(const float* __restrict__ x,
                                                 const float* __restrict__ Qw,
                                                 const float* __restrict__ Kw,
                                                 const float* __restrict__ Vw,
                                                 const float* __restrict__ Ow)
{
    const int idx = blockIdx.x * 256 + threadIdx.x;        // one float4 each
    if (idx < 2097152) {
        float4 v = ((const float4*)x)[idx];
        round_store4(v, g_xh + (size_t)idx * 4);
    } else {
        const int w = (idx - 2097152) >> 18;
        const size_t off = (size_t)((idx - 2097152) & 262143);
        const float* src = (w == 0) ? Qw : (w == 1) ? Kw : (w == 2) ? Vw : Ow;
        float4 v = ((const float4*)src)[off];
        round_store4(v, g_wh[w] + off * 4);
    }
}

// ---------------- 1-term fp16 GEMM: C = Ah @ Bh^T ----------------------------
// Block tile 128x128, BK=32, 128 threads = 4 warps (2m x 2n), warp tile 64x64.
#define SSTR 40
#define GBUF (128 * SSTR)
#define GSTG (2 * GBUF)               // Ah, Bh
#define GEMM_SMEM (2 * GSTG * 2)      // 40960 bytes

__device__ __forceinline__ void gemm_hf_body(const __half* __restrict__ Agh,
                                             const __half* __restrict__ Bgh,
                                             int m0, int n0,
                                             float (&c)[4][8][4],
                                             __half* sm)
{
    const int tid  = threadIdx.x;
    const int lane = tid & 31;
    const int warp = tid >> 5;
    const int wm   = (warp >> 1) * 64;
    const int wn   = (warp & 1) * 64;

    const int aoff = ((lane & 7) + ((lane >> 3) & 1) * 8) * SSTR + (lane >> 4) * 8;
    const int boff = ((lane & 7) + (lane >> 4) * 8) * SSTR + ((lane >> 3) & 1) * 8;

    int rowL[4], colL[4];
    #pragma unroll
    for (int u = 0; u < 4; u++) {
        const int idx = tid + 128 * u;
        rowL[u] = idx >> 2;
        colL[u] = (idx & 3) * 8;
    }

    {   // prologue: stage 0 <- k-tile 0
        __half* st = sm;
        #pragma unroll
        for (int u = 0; u < 4; u++) {
            const int so = rowL[u] * SSTR + colL[u];
            cp16(st + so,        Agh + (size_t)(m0 + rowL[u]) * D_MODEL + colL[u]);
            cp16(st + GBUF + so, Bgh + (size_t)(n0 + rowL[u]) * D_MODEL + colL[u]);
        }
        CP_COMMIT();
        CP_WAIT0();
    }
    __syncthreads();

    for (int kt = 0; kt < 32; kt++) {
        if (kt + 1 < 32) {
            __half* nx = sm + ((kt + 1) & 1) * GSTG;
            const int k0 = (kt + 1) * 32;
            #pragma unroll
            for (int u = 0; u < 4; u++) {
                const int so = rowL[u] * SSTR + colL[u];
                cp16(nx + so,        Agh + (size_t)(m0 + rowL[u]) * D_MODEL + k0 + colL[u]);
                cp16(nx + GBUF + so, Bgh + (size_t)(n0 + rowL[u]) * D_MODEL + k0 + colL[u]);
            }
            CP_COMMIT();
        }

        const __half* Ah = sm + (kt & 1) * GSTG;
        const __half* Bh = Ah + GBUF;

        #pragma unroll
        for (int ks = 0; ks < 2; ks++) {
            const int kk = ks * 16;
            unsigned a[4][4];
            #pragma unroll
            for (int i = 0; i < 4; i++)
                ldsm4(a[i], Ah + (wm + 16 * i) * SSTR + kk + aoff);
            #pragma unroll
            for (int p = 0; p < 4; p++) {
                unsigned bh[4];
                ldsm4(bh, Bh + (wn + 16 * p) * SSTR + kk + boff);
                const int j0 = 2 * p, j1 = j0 + 1;
                #pragma unroll
                for (int i = 0; i < 4; i++) {
                    mmaF(c[i][j0], a[i], bh[0], bh[1]);
                    mmaF(c[i][j1], a[i], bh[2], bh[3]);
                }
            }
        }
        CP_WAIT0();
        __syncthreads();
    }
}

// Fused QKV projection; blockIdx.z selects weight. All 1-term.
__global__ __launch_bounds__(128, 2) void gemm_qkv()
{
    extern __shared__ __half smg[];
    float c[4][8][4];
    #pragma unroll
    for (int i = 0; i < 4; i++)
        #pragma unroll
        for (int j = 0; j < 8; j++)
            #pragma unroll
            for (int q = 0; q < 4; q++) c[i][j][q] = 0.f;

    const int m0 = blockIdx.y * 128;
    const int n0 = blockIdx.x * 128;
    const int z  = blockIdx.z;

    gemm_hf_body(g_xh, g_wh[z], m0, n0, c, smg);

    const int tid  = threadIdx.x;
    const int lane = tid & 31;
    const int g = lane >> 2, t = lane & 3;
    const int warp = tid >> 5;
    const int wm = (warp >> 1) * 64, wn = (warp & 1) * 64;

    if (z == 2) {
        #define VS 136
        __half* vs = smg;
        __syncthreads();
        #pragma unroll
        for (int i = 0; i < 4; i++) {
            #pragma unroll
            for (int j = 0; j < 8; j++) {
                const int nn = wn + 8 * j + 2 * t;
                const int mm = wm + 16 * i + g;
                vs[(nn    ) * VS + mm    ] = __float2half_rn(c[i][j][0]);
                vs[(nn + 1) * VS + mm    ] = __float2half_rn(c[i][j][1]);
                vs[(nn    ) * VS + mm + 8] = __float2half_rn(c[i][j][2]);
                vs[(nn + 1) * VS + mm + 8] = __float2half_rn(c[i][j][3]);
            }
        }
        __syncthreads();
        const int r = tid;
        const int n = n0 + r;
        const int h = n >> 6, d = n & 63;
        const int b = m0 >> 11, s0 = m0 & 2047;
        __half* dst = g_vth + ((size_t)(b * NUM_HEADS + h) * D_HEAD + d) * SEQ + s0;
        const __half* src = vs + r * VS;
        #pragma unroll
        for (int u = 0; u < 16; u++)
            *(uint4*)&dst[8 * u] = *(const uint4*)&src[8 * u];
        #undef VS
    } else {
        __half* dst = (z == 0) ? g_qh : g_kh;
        #pragma unroll
        for (int i = 0; i < 4; i++) {
            #pragma unroll
            for (int j = 0; j < 8; j++) {
                const int n = n0 + wn + 8 * j + 2 * t;
                const int h = n >> 6, d = n & 63;
                const int r0 = m0 + wm + 16 * i + g;
                const int r1 = r0 + 8;
                const int b0 = r0 >> 11, s0 = r0 & 2047;
                const int b1 = r1 >> 11, s1 = r1 & 2047;
                const size_t i0 = ((size_t)(b0 * NUM_HEADS + h) * SEQ + s0) * D_HEAD + d;
                const size_t i1 = ((size_t)(b1 * NUM_HEADS + h) * SEQ + s1) * D_HEAD + d;
                *(unsigned*)&dst[i0] = pk(__float2half_rn(c[i][j][0]),
                                          __float2half_rn(c[i][j][1]));
                *(unsigned*)&dst[i1] = pk(__float2half_rn(c[i][j][2]),
                                          __float2half_rn(c[i][j][3]));
            }
        }
    }
}

// Output projection: out = ctx @ Ow^T, fp32 out. 1-term GEMM.
__global__ __launch_bounds__(128, 2) void gemm_out(float* __restrict__ out)
{
    extern __shared__ __half smg[];
    float c[4][8][4];
    #pragma unroll
    for (int i = 0; i < 4; i++)
        #pragma unroll
        for (int j = 0; j < 8; j++)
            #pragma unroll
            for (int q = 0; q < 4; q++) c[i][j][q] = 0.f;

    const int m0 = blockIdx.y * 128;
    const int n0 = blockIdx.x * 128;

    gemm_hf_body(g_ch, g_wh[3], m0, n0, c, smg);

    const int lane = threadIdx.x & 31;
    const int g = lane >> 2, t = lane & 3;
    const int warp = threadIdx.x >> 5;
    const int wm = (warp >> 1) * 64, wn = (warp & 1) * 64;

    #pragma unroll
    for (int i = 0; i < 4; i++) {
        #pragma unroll
        for (int j = 0; j < 8; j++) {
            const int n  = n0 + wn + 8 * j + 2 * t;
            const int r0 = m0 + wm + 16 * i + g;
            *(float2*)&out[(size_t)r0 * D_MODEL + n] = make_float2(c[i][j][0], c[i][j][1]);
            *(float2*)&out[(size_t)(r0 + 8) * D_MODEL + n] = make_float2(c[i][j][2], c[i][j][3]);
        }
    }
}

// ---------------- Flash attention: 256-q-row blocks, warp strip 32 rows ------
// Block = (b, h, 256-q-tile). 256 threads = 8 warps; warp owns rows
// [32w, 32w+32) as two 16-row m-blocks. KV tiles of 64. Each K/V ldsm4
// feeds 4 mma (2 m-blocks).
#define QSTR 72
#define TILEC (64 * QSTR)
#define ATTN_SMEM (8 * TILEC * 2)         // 73728 B: 2 KV stages + Ph(256 rows)

__global__ __launch_bounds__(256, 1) void attn_mma(const unsigned char* __restrict__ pm)
{
    extern __shared__ __half smb[];
    __half* stg0 = smb;                   // {Kh, Vth} stage 0
    __half* stg1 = smb + 2 * TILEC;       // stage 1
    __half* Ph   = smb + 4 * TILEC;       // P single (256 rows = 4 TILEC)

    const int qt = gridDim.x - 1 - blockIdx.x;   // heavy blocks first
    const int h  = blockIdx.y;
    const int b  = blockIdx.z;
    const int tid  = threadIdx.x;
    const int lane = tid & 31;
    const int warp = tid >> 5;
    const int g = lane >> 2, t = lane & 3;
    const size_t base = (size_t)(b * NUM_HEADS + h) * SEQ;

    const int rw = warp * 32;                    // warp's local q-row base
    const int Rg = qt * 256 + rw;                // global q-row base
    const int kt_max = 4 * qt + 3;

    const int aoffQ = ((lane & 7) + ((lane >> 3) & 1) * 8) * QSTR + (lane >> 4) * 8;
    const int boffQ = ((lane & 7) + (lane >> 4) * 8) * QSTR + ((lane >> 3) & 1) * 8;

    const int krow = tid >> 2;
    const int kcs  = (tid & 3) * 16;
    const int kso  = krow * QSTR + kcs;
    const size_t vbase = ((size_t)(b * NUM_HEADS + h) * D_HEAD + krow) * SEQ + kcs;
    const size_t kbase = (base + krow) * D_HEAD + kcs;

    // ---- stage Q[256][64] into smb[0..4T), move to regs ----
    {
        #pragma unroll
        for (int u = 0; u < 2; u++) {
            const int row = 128 * u + (tid >> 1);
            const int cs  = (tid & 1) * 32;
            const size_t ga = (base + (size_t)qt * 256 + row) * D_HEAD + cs;
            const int so = row * QSTR + cs;
            #pragma unroll
            for (int v = 0; v < 4; v++)
                cp16(&smb[so + 8 * v], &g_qh[ga + 8 * v]);
        }
        CP_COMMIT();
        CP_WAIT0();
    }
    __syncthreads();

    unsigned qh[2][4][4];
    #pragma unroll
    for (int i = 0; i < 2; i++)
        #pragma unroll
        for (int ks = 0; ks < 4; ks++)
            ldsm4(qh[i][ks], smb + (rw + 16 * i) * QSTR + 16 * ks + aoffQ);
    __syncthreads();                      // smem free for KV stages

    // ---- prologue: KV(0) into stg0 ----
    {
        cp16(&stg0[kso],         &g_kh[kbase]);  cp16(&stg0[kso + 8],         &g_kh[kbase + 8]);
        cp16(&stg0[TILEC + kso], &g_vth[vbase]); cp16(&stg0[TILEC + kso + 8], &g_vth[vbase + 8]);
        CP_COMMIT();
    }

    float o[2][8][4];
    float m_i[2][2] = {{-1e30f, -1e30f}, {-1e30f, -1e30f}};
    float l_i[2][2] = {{0.f, 0.f}, {0.f, 0.f}};
    #pragma unroll
    for (int i = 0; i < 2; i++)
        #pragma unroll
        for (int j = 0; j < 8; j++)
            #pragma unroll
            for (int q = 0; q < 4; q++) o[i][j][q] = 0.f;

    for (int kt = 0; kt <= kt_max; kt++) {
        if (kt < kt_max) {
            __half* nx = ((kt + 1) & 1) ? stg1 : stg0;
            const size_t gk = kbase + (size_t)(kt + 1) * 64 * D_HEAD;
            const size_t gv = vbase + (size_t)(kt + 1) * 64;
            cp16(&nx[kso],         &g_kh[gk]);  cp16(&nx[kso + 8],         &g_kh[gk + 8]);
            cp16(&nx[TILEC + kso], &g_vth[gv]); cp16(&nx[TILEC + kso + 8], &g_vth[gv + 8]);
            CP_COMMIT();
            CP_WAIT1();                    // KV(kt) complete
        } else {
            CP_WAIT0();
        }
        __syncthreads();

        const int C0 = kt * 64;
        if (C0 <= Rg + 31) {               // warp strip not fully masked
            const __half* Kh = (kt & 1) ? stg1 : stg0;
            const __half* Vh = Kh + TILEC;

            float s[2][8][4];
            #pragma unroll
            for (int i = 0; i < 2; i++)
                #pragma unroll
                for (int j = 0; j < 8; j++)
                    #pragma unroll
                    for (int q = 0; q < 4; q++) s[i][j][q] = 0.f;

            // ---- S = Q @ Kh^T (K frags shared across 2 m-blocks) ----
            #pragma unroll
            for (int ks = 0; ks < 4; ks++) {
                const int kk = 16 * ks;
                #pragma unroll
                for (int p = 0; p < 4; p++) {
                    unsigned bh[4];
                    ldsm4(bh, Kh + (16 * p) * QSTR + kk + boffQ);
                    const int j0 = 2 * p, j1 = j0 + 1;
                    mmaF(s[0][j0], qh[0][ks], bh[0], bh[1]);
                    mmaF(s[0][j1], qh[0][ks], bh[2], bh[3]);
                    mmaF(s[1][j0], qh[1][ks], bh[0], bh[1]);
                    mmaF(s[1][j1], qh[1][ks], bh[2], bh[3]);
                }
            }

            // ---- scale + masks + online softmax per m-block ----
            const unsigned char* pmb = pm + (size_t)b * SEQ + C0;
            #pragma unroll
            for (int i = 0; i < 2; i++) {
                const int r0 = Rg + 16 * i + g, r1 = r0 + 8;
                #pragma unroll
                for (int j = 0; j < 8; j++) {
                    const int c0 = C0 + 8 * j + 2 * t, c1 = c0 + 1;
                    const bool p0 = pmb[8 * j + 2 * t] != 0;
                    const bool p1 = pmb[8 * j + 2 * t + 1] != 0;
                    float v;
                    v = s[i][j][0] * SCALE_LOG2E; if (c0 > r0 || p0) v = -1e30f; s[i][j][0] = v;
                    v = s[i][j][1] * SCALE_LOG2E; if (c1 > r0 || p1) v = -1e30f; s[i][j][1] = v;
                    v = s[i][j][2] * SCALE_LOG2E; if (c0 > r1 || p0) v = -1e30f; s[i][j][2] = v;
                    v = s[i][j][3] * SCALE_LOG2E; if (c1 > r1 || p1) v = -1e30f; s[i][j][3] = v;
                }
                #pragma unroll
                for (int rr = 0; rr < 2; rr++) {
                    float rm = -1e30f;
                    #pragma unroll
                    for (int j = 0; j < 8; j++)
                        rm = fmaxf(rm, fmaxf(s[i][j][2 * rr], s[i][j][2 * rr + 1]));
                    rm = fmaxf(rm, __shfl_xor_sync(0xffffffffu, rm, 1));
                    rm = fmaxf(rm, __shfl_xor_sync(0xffffffffu, rm, 2));
                    const float mn    = fmaxf(m_i[i][rr], rm);
                    const float alpha = exp2_fast(m_i[i][rr] - mn);
                    m_i[i][rr] = mn;
                    float rs = 0.f;
                    #pragma unroll
                    for (int j = 0; j < 8; j++) {
                        s[i][j][2 * rr    ] = exp2_fast(s[i][j][2 * rr    ] - mn);
                        s[i][j][2 * rr + 1] = exp2_fast(s[i][j][2 * rr + 1] - mn);
                        rs += s[i][j][2 * rr] + s[i][j][2 * rr + 1];
                    }
                    rs += __shfl_xor_sync(0xffffffffu, rs, 1);
                    rs += __shfl_xor_sync(0xffffffffu, rs, 2);
                    l_i[i][rr] = l_i[i][rr] * alpha + rs;
                    #pragma unroll
                    for (int j = 0; j < 8; j++) {
                        o[i][j][2 * rr    ] *= alpha;
                        o[i][j][2 * rr + 1] *= alpha;
                    }
                }
            }

            // ---- write P single (warp-private rows) ----
            #pragma unroll
            for (int i = 0; i < 2; i++)
                #pragma unroll
                for (int j = 0; j < 8; j++) {
                    const int p0 = (rw + 16 * i + g) * QSTR + 8 * j + 2 * t;
                    const int p1 = p0 + 8 * QSTR;
                    *(unsigned*)&Ph[p0] = pk(__float2half_rn(s[i][j][0]),
                                             __float2half_rn(s[i][j][1]));
                    *(unsigned*)&Ph[p1] = pk(__float2half_rn(s[i][j][2]),
                                             __float2half_rn(s[i][j][3]));
                }
            __syncwarp();

            // ---- O += P @ Vh (V frags shared across 2 m-blocks) ----
            #pragma unroll
            for (int ks = 0; ks < 4; ks++) {
                const int kk = 16 * ks;
                unsigned ph[2][4];
                ldsm4(ph[0], Ph + (rw     ) * QSTR + kk + aoffQ);
                ldsm4(ph[1], Ph + (rw + 16) * QSTR + kk + aoffQ);
                #pragma unroll
                for (int p = 0; p < 4; p++) {
                    unsigned bh[4];
                    ldsm4(bh, Vh + (16 * p) * QSTR + kk + boffQ);
                    const int j0 = 2 * p, j1 = j0 + 1;
                    mmaF(o[0][j0], ph[0], bh[0], bh[1]);
                    mmaF(o[0][j1], ph[0], bh[2], bh[3]);
                    mmaF(o[1][j0], ph[1], bh[0], bh[1]);
                    mmaF(o[1][j1], ph[1], bh[2], bh[3]);
                }
            }
        }
        __syncthreads();
    }

    // ---- normalize + write ctx single [b, s, h*64 + col] ----
    #pragma unroll
    for (int i = 0; i < 2; i++) {
        const float inv0 = 1.f / l_i[i][0];
        const float inv1 = 1.f / l_i[i][1];
        const int row0 = qt * 256 + rw + 16 * i + g;
        const size_t d0 = ((size_t)b * SEQ + row0    ) * D_MODEL + h * D_HEAD;
        const size_t d1 = ((size_t)b * SEQ + row0 + 8) * D_MODEL + h * D_HEAD;
        #pragma unroll
        for (int j = 0; j < 8; j++) {
            const int cidx = 8 * j + 2 * t;
            *(unsigned*)&g_ch[d0 + cidx] = pk(__float2half_rn(o[i][j][0] * inv0),
                                              __float2half_rn(o[i][j][1] * inv0));
            *(unsigned*)&g_ch[d1 + cidx] = pk(__float2half_rn(o[i][j][2] * inv1),
                                              __float2half_rn(o[i][j][3] * inv1));
        }
    }
}

// ---------------- launch ----------------------------------------------------
extern "C" void kernel_launch(void* const* d_in, const int* in_sizes, int n_in,
                              void* d_out, int out_size)
{
    (void)in_sizes; (void)n_in; (void)out_size;
    const float* x  = (const float*)d_in[0];
    const float* Qw = (const float*)d_in[1];
    const float* Kw = (const float*)d_in[2];
    const float* Vw = (const float*)d_in[3];
    const float* Ow = (const float*)d_in[4];
    const unsigned char* pm = (const unsigned char*)d_in[5];
    float* out = (float*)d_out;

    cudaFuncSetAttribute(attn_mma, cudaFuncAttributeMaxDynamicSharedMemorySize, ATTN_SMEM);
    cudaFuncSetAttribute(gemm_qkv, cudaFuncAttributeMaxDynamicSharedMemorySize, GEMM_SMEM);
    cudaFuncSetAttribute(gemm_out, cudaFuncAttributeMaxDynamicSharedMemorySize, GEMM_SMEM);

    split_all<<<12288, 256>>>(x, Qw, Kw, Vw, Ow);

    dim3 gq(D_MODEL / 128, MTOT / 128, 3);        // 8 x 64 x 3
    gemm_qkv<<<gq, 128, GEMM_SMEM>>>();

    dim3 ga(SEQ / 256, NUM_HEADS, BATCH);         // 8 x 16 x 4
    attn_mma<<<ga, 256, ATTN_SMEM>>>(pm);

    dim3 go(D_MODEL / 128, MTOT / 128);           // 8 x 64
    gemm_out<<<go, 128, GEMM_SMEM>>>(out);
}

// round 16
// speedup vs baseline: 1.1324x; 1.1324x over previous
#include <cuda_runtime.h>
#include <cuda_fp16.h>
#include <cstdint>

#define D_MODEL   1024
#define NUM_HEADS 16
#define D_HEAD    64
#define BATCH     4
#define SEQ       2048
#define MTOT      (BATCH * SEQ)   // 8192
#define QKV_EL    (BATCH * NUM_HEADS * SEQ * D_HEAD)   // 8388608

// ---------------- scratch (device globals: allocation-guard safe) ----------
__device__ __half g_xh[MTOT * D_MODEL];                // x single fp16
__device__ __half g_wh[4][D_MODEL * D_MODEL];          // weights single fp16
__device__ __half g_qh[QKV_EL];                        // [b,h,s,d] single
__device__ __half g_kh[QKV_EL];                        // [b,h,s,d] single
__device__ __half g_vth[QKV_EL];                       // [b,h,d,s] single
__device__ __half g_ch[MTOT * D_MODEL];                // ctx single

// ---------------- helpers ----------------------------------------------------
__device__ __forceinline__ unsigned pk(__half a, __half b) {
    return (unsigned)__half_as_ushort(a) | ((unsigned)__half_as_ushort(b) << 16);
}
__device__ __forceinline__ unsigned pkf(float a, float b) {
    return pk(__float2half_rn(a), __float2half_rn(b));
}
__device__ __forceinline__ void round_store4(float4 v, __half* hp) {
    *(uint2*)hp = make_uint2(pkf(v.x, v.y), pkf(v.z, v.w));
}
// fp32-accumulator mma (fp16 inputs)
__device__ __forceinline__ void mmaF(float* c, const unsigned* a, unsigned b0, unsigned b1) {
    asm volatile(
        "mma.sync.aligned.m16n8k16.row.col.f32.f16.f16.f32 "
        "{%0,%1,%2,%3}, {%4,%5,%6,%7}, {%8,%9}, {%0,%1,%2,%3};"
        : "+f"(c[0]), "+f"(c[1]), "+f"(c[2]), "+f"(c[3])
        : "r"(a[0]), "r"(a[1]), "r"(a[2]), "r"(a[3]), "r"(b0), "r"(b1));
}
__device__ __forceinline__ void ldsm4(unsigned r[4], const __half* p) {
    unsigned a = (unsigned)__cvta_generic_to_shared(p);
    asm volatile("ldmatrix.sync.aligned.m8n8.x4.shared.b16 {%0,%1,%2,%3}, [%4];"
                 : "=r"(r[0]), "=r"(r[1]), "=r"(r[2]), "=r"(r[3]) : "r"(a));
}
__device__ __forceinline__ void cp16(__half* s, const __half* g) {
    unsigned sa = (unsigned)__cvta_generic_to_shared(s);
    asm volatile("cp.async.cg.shared.global [%0], [%1], 16;" :: "r"(sa), "l"(g));
}
#define CP_COMMIT() asm volatile("cp.async.commit_group;")
#define CP_WAIT0()  asm volatile("cp.async.wait_group 0;")
#define CP_WAIT1()  asm volatile("cp.async.wait_group 1;")

// fast exp2 on the FMA pipe (MUFU-free)
__device__ __forceinline__ float exp2_fast(float y) {
    y = fmaxf(y, -120.f);
    float z = y + 12582912.f;
    int   e = __float_as_int(z);
    float f = y - (z - 12582912.f);
    float p = 1.f + f * (0.6931471805599453f + f * (0.2402265069591007f +
              f * (0.0555041086648216f + f * (0.0096181291076285f +
              f * 0.0013333558146429f))));
    return __int_as_float(__float_as_int(p) + (e << 23));
}
#define SCALE_LOG2E 0.18033688011112042f   // 0.125 * log2(e)

// ---------------- one-shot fp16 rounding of x + weights ----------------------
__global__ __launch_bounds__(256) void split_all(const float* __restrict__ x,
                                                 const float* __restrict__ Qw,
                                                 const float* __restrict__ Kw,
                                                 const float* __restrict__ Vw,
                                                 const float* __restrict__ Ow)
{
    const int idx = blockIdx.x * 256 + threadIdx.x;        // one float4 each
    if (idx < 2097152) {
        float4 v = ((const float4*)x)[idx];
        round_store4(v, g_xh + (size_t)idx * 4);
    } else {
        const int w = (idx - 2097152) >> 18;
        const size_t off = (size_t)((idx - 2097152) & 262143);
        const float* src = (w == 0) ? Qw : (w == 1) ? Kw : (w == 2) ? Vw : Ow;
        float4 v = ((const float4*)src)[off];
        round_store4(v, g_wh[w] + off * 4);
    }
}

// ---------------- 1-term fp16 GEMM: C = Ah @ Bh^T ----------------------------
// Block tile 128x128, BK=32, 128 threads = 4 warps (2m x 2n), warp tile 64x64.
#define SSTR 40
#define GBUF (128 * SSTR)
#define GSTG (2 * GBUF)               // Ah, Bh
#define GEMM_SMEM (2 * GSTG * 2)      // 40960 bytes

__device__ __forceinline__ void gemm_hf_body(const __half* __restrict__ Agh,
                                             const __half* __restrict__ Bgh,
                                             int m0, int n0,
                                             float (&c)[4][8][4],
                                             __half* sm)
{
    const int tid  = threadIdx.x;
    const int lane = tid & 31;
    const int warp = tid >> 5;
    const int wm   = (warp >> 1) * 64;
    const int wn   = (warp & 1) * 64;

    const int aoff = ((lane & 7) + ((lane >> 3) & 1) * 8) * SSTR + (lane >> 4) * 8;
    const int boff = ((lane & 7) + (lane >> 4) * 8) * SSTR + ((lane >> 3) & 1) * 8;

    int rowL[4], colL[4];
    #pragma unroll
    for (int u = 0; u < 4; u++) {
        const int idx = tid + 128 * u;
        rowL[u] = idx >> 2;
        colL[u] = (idx & 3) * 8;
    }

    {   // prologue: stage 0 <- k-tile 0
        __half* st = sm;
        #pragma unroll
        for (int u = 0; u < 4; u++) {
            const int so = rowL[u] * SSTR + colL[u];
            cp16(st + so,        Agh + (size_t)(m0 + rowL[u]) * D_MODEL + colL[u]);
            cp16(st + GBUF + so, Bgh + (size_t)(n0 + rowL[u]) * D_MODEL + colL[u]);
        }
        CP_COMMIT();
        CP_WAIT0();
    }
    __syncthreads();

    for (int kt = 0; kt < 32; kt++) {
        if (kt + 1 < 32) {
            __half* nx = sm + ((kt + 1) & 1) * GSTG;
            const int k0 = (kt + 1) * 32;
            #pragma unroll
            for (int u = 0; u < 4; u++) {
                const int so = rowL[u] * SSTR + colL[u];
                cp16(nx + so,        Agh + (size_t)(m0 + rowL[u]) * D_MODEL + k0 + colL[u]);
                cp16(nx + GBUF + so, Bgh + (size_t)(n0 + rowL[u]) * D_MODEL + k0 + colL[u]);
            }
            CP_COMMIT();
        }

        const __half* Ah = sm + (kt & 1) * GSTG;
        const __half* Bh = Ah + GBUF;

        #pragma unroll
        for (int ks = 0; ks < 2; ks++) {
            const int kk = ks * 16;
            unsigned a[4][4];
            #pragma unroll
            for (int i = 0; i < 4; i++)
                ldsm4(a[i], Ah + (wm + 16 * i) * SSTR + kk + aoff);
            #pragma unroll
            for (int p = 0; p < 4; p++) {
                unsigned bh[4];
                ldsm4(bh, Bh + (wn + 16 * p) * SSTR + kk + boff);
                const int j0 = 2 * p, j1 = j0 + 1;
                #pragma unroll
                for (int i = 0; i < 4; i++) {
                    mmaF(c[i][j0], a[i], bh[0], bh[1]);
                    mmaF(c[i][j1], a[i], bh[2], bh[3]);
                }
            }
        }
        CP_WAIT0();
        __syncthreads();
    }
}

// Fused QKV projection; blockIdx.z selects weight. All 1-term.
__global__ __launch_bounds__(128, 2) void gemm_qkv()
{
    extern __shared__ __half smg[];
    float c[4][8][4];
    #pragma unroll
    for (int i = 0; i < 4; i++)
        #pragma unroll
        for (int j = 0; j < 8; j++)
            #pragma unroll
            for (int q = 0; q < 4; q++) c[i][j][q] = 0.f;

    const int m0 = blockIdx.y * 128;
    const int n0 = blockIdx.x * 128;
    const int z  = blockIdx.z;

    gemm_hf_body(g_xh, g_wh[z], m0, n0, c, smg);

    const int tid  = threadIdx.x;
    const int lane = tid & 31;
    const int g = lane >> 2, t = lane & 3;
    const int warp = tid >> 5;
    const int wm = (warp >> 1) * 64, wn = (warp & 1) * 64;

    if (z == 2) {
        #define VS 136
        __half* vs = smg;
        __syncthreads();
        #pragma unroll
        for (int i = 0; i < 4; i++) {
            #pragma unroll
            for (int j = 0; j < 8; j++) {
                const int nn = wn + 8 * j + 2 * t;
                const int mm = wm + 16 * i + g;
                vs[(nn    ) * VS + mm    ] = __float2half_rn(c[i][j][0]);
                vs[(nn + 1) * VS + mm    ] = __float2half_rn(c[i][j][1]);
                vs[(nn    ) * VS + mm + 8] = __float2half_rn(c[i][j][2]);
                vs[(nn + 1) * VS + mm + 8] = __float2half_rn(c[i][j][3]);
            }
        }
        __syncthreads();
        const int r = tid;
        const int n = n0 + r;
        const int h = n >> 6, d = n & 63;
        const int b = m0 >> 11, s0 = m0 & 2047;
        __half* dst = g_vth + ((size_t)(b * NUM_HEADS + h) * D_HEAD + d) * SEQ + s0;
        const __half* src = vs + r * VS;
        #pragma unroll
        for (int u = 0; u < 16; u++)
            *(uint4*)&dst[8 * u] = *(const uint4*)&src[8 * u];
        #undef VS
    } else {
        __half* dst = (z == 0) ? g_qh : g_kh;
        #pragma unroll
        for (int i = 0; i < 4; i++) {
            #pragma unroll
            for (int j = 0; j < 8; j++) {
                const int n = n0 + wn + 8 * j + 2 * t;
                const int h = n >> 6, d = n & 63;
                const int r0 = m0 + wm + 16 * i + g;
                const int r1 = r0 + 8;
                const int b0 = r0 >> 11, s0 = r0 & 2047;
                const int b1 = r1 >> 11, s1 = r1 & 2047;
                const size_t i0 = ((size_t)(b0 * NUM_HEADS + h) * SEQ + s0) * D_HEAD + d;
                const size_t i1 = ((size_t)(b1 * NUM_HEADS + h) * SEQ + s1) * D_HEAD + d;
                *(unsigned*)&dst[i0] = pkf(c[i][j][0], c[i][j][1]);
                *(unsigned*)&dst[i1] = pkf(c[i][j][2], c[i][j][3]);
            }
        }
    }
}

// Output projection: out = ctx @ Ow^T, fp32 out. 1-term GEMM.
__global__ __launch_bounds__(128, 2) void gemm_out(float* __restrict__ out)
{
    extern __shared__ __half smg[];
    float c[4][8][4];
    #pragma unroll
    for (int i = 0; i < 4; i++)
        #pragma unroll
        for (int j = 0; j < 8; j++)
            #pragma unroll
            for (int q = 0; q < 4; q++) c[i][j][q] = 0.f;

    const int m0 = blockIdx.y * 128;
    const int n0 = blockIdx.x * 128;

    gemm_hf_body(g_ch, g_wh[3], m0, n0, c, smg);

    const int lane = threadIdx.x & 31;
    const int g = lane >> 2, t = lane & 3;
    const int warp = threadIdx.x >> 5;
    const int wm = (warp >> 1) * 64, wn = (warp & 1) * 64;

    #pragma unroll
    for (int i = 0; i < 4; i++) {
        #pragma unroll
        for (int j = 0; j < 8; j++) {
            const int n  = n0 + wn + 8 * j + 2 * t;
            const int r0 = m0 + wm + 16 * i + g;
            *(float2*)&out[(size_t)r0 * D_MODEL + n] = make_float2(c[i][j][0], c[i][j][1]);
            *(float2*)&out[(size_t)(r0 + 8) * D_MODEL + n] = make_float2(c[i][j][2], c[i][j][3]);
        }
    }
}

// ---------------- Flash attention (R14 shape) + register-direct P ------------
// Block = (b, h, 128-q-tile). 256 threads = 8 warps, warp strip 16 rows.
// P never touches smem: the S C-fragment IS the PV A-fragment layout.
#define QSTR 72
#define TILEC (64 * QSTR)
#define ATTN_SMEM (4 * TILEC * 2)         // 36864 bytes: 2 KV stages only

__global__ __launch_bounds__(256, 2) void attn_mma(const unsigned char* __restrict__ pm)
{
    extern __shared__ __half smb[];
    __half* stg0 = smb;                   // {Kh, Vth} stage 0
    __half* stg1 = smb + 2 * TILEC;       // stage 1

    const int qt = gridDim.x - 1 - blockIdx.x;   // heavy blocks first
    const int h  = blockIdx.y;
    const int b  = blockIdx.z;
    const int tid  = threadIdx.x;
    const int lane = tid & 31;
    const int warp = tid >> 5;
    const int g = lane >> 2, t = lane & 3;
    const size_t base = (size_t)(b * NUM_HEADS + h) * SEQ;

    const int rw = warp * 16;
    const int Rg = qt * 128 + rw;
    const int kt_max = 2 * qt + 1;

    const int aoffQ = ((lane & 7) + ((lane >> 3) & 1) * 8) * QSTR + (lane >> 4) * 8;
    const int boffQ = ((lane & 7) + (lane >> 4) * 8) * QSTR + ((lane >> 3) & 1) * 8;

    const int krow = tid >> 2;
    const int kcs  = (tid & 3) * 16;
    const int kso  = krow * QSTR + kcs;
    const size_t vbase = ((size_t)(b * NUM_HEADS + h) * D_HEAD + krow) * SEQ + kcs;
    const size_t kbase = (base + krow) * D_HEAD + kcs;

    // ---- stage Q single into smb[0..2T), move to regs ----
    {
        const int row = tid >> 1, cs = (tid & 1) * 32;
        const size_t ga = (base + (size_t)qt * 128 + row) * D_HEAD + cs;
        const int so = row * QSTR + cs;
        #pragma unroll
        for (int u = 0; u < 4; u++)
            cp16(&smb[so + 8 * u], &g_qh[ga + 8 * u]);
        CP_COMMIT();
        CP_WAIT0();
    }
    __syncthreads();

    unsigned qh[4][4];
    #pragma unroll
    for (int ks = 0; ks < 4; ks++)
        ldsm4(qh[ks], smb + rw * QSTR + 16 * ks + aoffQ);
    __syncthreads();                      // smem free for KV stages

    // ---- prologue: KV(0) into stg0 ----
    {
        cp16(&stg0[kso],         &g_kh[kbase]);  cp16(&stg0[kso + 8],         &g_kh[kbase + 8]);
        cp16(&stg0[TILEC + kso], &g_vth[vbase]); cp16(&stg0[TILEC + kso + 8], &g_vth[vbase + 8]);
        CP_COMMIT();
    }

    float o[8][4];
    float m_i[2] = {-1e30f, -1e30f};
    float l_i[2] = {0.f, 0.f};
    #pragma unroll
    for (int j = 0; j < 8; j++)
        #pragma unroll
        for (int q = 0; q < 4; q++) o[j][q] = 0.f;

    for (int kt = 0; kt <= kt_max; kt++) {
        if (kt < kt_max) {
            __half* nx = ((kt + 1) & 1) ? stg1 : stg0;
            const size_t gk = kbase + (size_t)(kt + 1) * 64 * D_HEAD;
            const size_t gv = vbase + (size_t)(kt + 1) * 64;
            cp16(&nx[kso],         &g_kh[gk]);  cp16(&nx[kso + 8],         &g_kh[gk + 8]);
            cp16(&nx[TILEC + kso], &g_vth[gv]); cp16(&nx[TILEC + kso + 8], &g_vth[gv + 8]);
            CP_COMMIT();
            CP_WAIT1();                    // KV(kt) complete
        } else {
            CP_WAIT0();
        }
        __syncthreads();

        const int C0 = kt * 64;
        if (C0 <= Rg + 15) {
            const __half* Kh = (kt & 1) ? stg1 : stg0;
            const __half* Vh = Kh + TILEC;

            float s[8][4];
            #pragma unroll
            for (int j = 0; j < 8; j++)
                #pragma unroll
                for (int q = 0; q < 4; q++) s[j][q] = 0.f;

            // ---- S = Q @ Kh^T (1-term) ----
            #pragma unroll
            for (int ks = 0; ks < 4; ks++) {
                const int kk = 16 * ks;
                #pragma unroll
                for (int p = 0; p < 2; p++) {
                    unsigned bh0[4], bh1[4];
                    ldsm4(bh0, Kh + (32 * p     ) * QSTR + kk + boffQ);
                    ldsm4(bh1, Kh + (32 * p + 16) * QSTR + kk + boffQ);
                    const int j0 = 4 * p;
                    mmaF(s[j0 + 0], qh[ks], bh0[0], bh0[1]);
                    mmaF(s[j0 + 1], qh[ks], bh0[2], bh0[3]);
                    mmaF(s[j0 + 2], qh[ks], bh1[0], bh1[1]);
                    mmaF(s[j0 + 3], qh[ks], bh1[2], bh1[3]);
                }
            }

            // ---- scale (log2 domain) + causal + padding masks ----
            const unsigned char* pmb = pm + (size_t)b * SEQ + C0;
            const int r0 = Rg + g, r1 = r0 + 8;
            #pragma unroll
            for (int j = 0; j < 8; j++) {
                const int c0 = C0 + 8 * j + 2 * t, c1 = c0 + 1;
                const bool p0 = pmb[8 * j + 2 * t] != 0;
                const bool p1 = pmb[8 * j + 2 * t + 1] != 0;
                float v;
                v = s[j][0] * SCALE_LOG2E; if (c0 > r0 || p0) v = -1e30f; s[j][0] = v;
                v = s[j][1] * SCALE_LOG2E; if (c1 > r0 || p1) v = -1e30f; s[j][1] = v;
                v = s[j][2] * SCALE_LOG2E; if (c0 > r1 || p0) v = -1e30f; s[j][2] = v;
                v = s[j][3] * SCALE_LOG2E; if (c1 > r1 || p1) v = -1e30f; s[j][3] = v;
            }

            // ---- online softmax, base-2, FMA-pipe exp ----
            #pragma unroll
            for (int rr = 0; rr < 2; rr++) {
                float rm = -1e30f;
                #pragma unroll
                for (int j = 0; j < 8; j++)
                    rm = fmaxf(rm, fmaxf(s[j][2 * rr], s[j][2 * rr + 1]));
                rm = fmaxf(rm, __shfl_xor_sync(0xffffffffu, rm, 1));
                rm = fmaxf(rm, __shfl_xor_sync(0xffffffffu, rm, 2));
                const float mn    = fmaxf(m_i[rr], rm);
                const float alpha = exp2_fast(m_i[rr] - mn);
                m_i[rr] = mn;
                float rs = 0.f;
                #pragma unroll
                for (int j = 0; j < 8; j++) {
                    s[j][2 * rr    ] = exp2_fast(s[j][2 * rr    ] - mn);
                    s[j][2 * rr + 1] = exp2_fast(s[j][2 * rr + 1] - mn);
                    rs += s[j][2 * rr] + s[j][2 * rr + 1];
                }
                rs += __shfl_xor_sync(0xffffffffu, rs, 1);
                rs += __shfl_xor_sync(0xffffffffu, rs, 2);
                l_i[rr] = l_i[rr] * alpha + rs;
                #pragma unroll
                for (int j = 0; j < 8; j++) {
                    o[j][2 * rr    ] *= alpha;
                    o[j][2 * rr + 1] *= alpha;
                }
            }

            // ---- O += P @ Vh: P built in-register from S C-fragments ----
            // C-frag (rows g/g+8, cols 8j+2t) == A-frag (rows g/g+8, k=16ks+2t):
            //   a0 = s[2ks][0:1], a1 = s[2ks][2:3], a2 = s[2ks+1][0:1], a3 = s[2ks+1][2:3]
            #pragma unroll
            for (int ks = 0; ks < 4; ks++) {
                const int kk = 16 * ks;
                unsigned ph[4];
                ph[0] = pkf(s[2 * ks    ][0], s[2 * ks    ][1]);
                ph[1] = pkf(s[2 * ks    ][2], s[2 * ks    ][3]);
                ph[2] = pkf(s[2 * ks + 1][0], s[2 * ks + 1][1]);
                ph[3] = pkf(s[2 * ks + 1][2], s[2 * ks + 1][3]);
                #pragma unroll
                for (int p = 0; p < 2; p++) {
                    unsigned bh0[4], bh1[4];
                    ldsm4(bh0, Vh + (32 * p     ) * QSTR + kk + boffQ);
                    ldsm4(bh1, Vh + (32 * p + 16) * QSTR + kk + boffQ);
                    const int j0 = 4 * p;
                    mmaF(o[j0 + 0], ph, bh0[0], bh0[1]);
                    mmaF(o[j0 + 1], ph, bh0[2], bh0[3]);
                    mmaF(o[j0 + 2], ph, bh1[0], bh1[1]);
                    mmaF(o[j0 + 3], ph, bh1[2], bh1[3]);
                }
            }
        }
        __syncthreads();
    }

    // ---- normalize + write ctx single [b, s, h*64 + col] ----
    const float inv0 = 1.f / l_i[0];
    const float inv1 = 1.f / l_i[1];
    const int row0 = qt * 128 + rw + g;
    const size_t d0 = ((size_t)b * SEQ + row0    ) * D_MODEL + h * D_HEAD;
    const size_t d1 = ((size_t)b * SEQ + row0 + 8) * D_MODEL + h * D_HEAD;
    #pragma unroll
    for (int j = 0; j < 8; j++) {
        const int cidx = 8 * j + 2 * t;
        *(unsigned*)&g_ch[d0 + cidx] = pkf(o[j][0] * inv0, o[j][1] * inv0);
        *(unsigned*)&g_ch[d1 + cidx] = pkf(o[j][2] * inv1, o[j][3] * inv1);
    }
}

// ---------------- launch ----------------------------------------------------
extern "C" void kernel_launch(void* const* d_in, const int* in_sizes, int n_in,
                              void* d_out, int out_size)
{
    (void)in_sizes; (void)n_in; (void)out_size;
    const float* x  = (const float*)d_in[0];
    const float* Qw = (const float*)d_in[1];
    const float* Kw = (const float*)d_in[2];
    const float* Vw = (const float*)d_in[3];
    const float* Ow = (const float*)d_in[4];
    const unsigned char* pm = (const unsigned char*)d_in[5];
    float* out = (float*)d_out;

    cudaFuncSetAttribute(attn_mma, cudaFuncAttributeMaxDynamicSharedMemorySize, ATTN_SMEM);
    cudaFuncSetAttribute(gemm_qkv, cudaFuncAttributeMaxDynamicSharedMemorySize, GEMM_SMEM);
    cudaFuncSetAttribute(gemm_out, cudaFuncAttributeMaxDynamicSharedMemorySize, GEMM_SMEM);

    split_all<<<12288, 256>>>(x, Qw, Kw, Vw, Ow);

    dim3 gq(D_MODEL / 128, MTOT / 128, 3);        // 8 x 64 x 3
    gemm_qkv<<<gq, 128, GEMM_SMEM>>>();

    dim3 ga(SEQ / 128, NUM_HEADS, BATCH);         // 16 x 16 x 4
    attn_mma<<<ga, 256, ATTN_SMEM>>>(pm);

    dim3 go(D_MODEL / 128, MTOT / 128);           // 8 x 64
    gemm_out<<<go, 128, GEMM_SMEM>>>(out);
}

// round 17
// speedup vs baseline: 1.1336x; 1.0011x over previous
#include <cuda_runtime.h>
#include <cuda_fp16.h>
#include <cstdint>

#define D_MODEL   1024
#define NUM_HEADS 16
#define D_HEAD    64
#define BATCH     4
#define SEQ       2048
#define MTOT      (BATCH * SEQ)   // 8192
#define QKV_EL    (BATCH * NUM_HEADS * SEQ * D_HEAD)   // 8388608

// ---------------- scratch (device globals: allocation-guard safe) ----------
__device__ __half g_xh[MTOT * D_MODEL];                // x single fp16
__device__ __half g_wh[4][D_MODEL * D_MODEL];          // weights single fp16
__device__ __half g_qh[QKV_EL];                        // [b,h,s,d] single
__device__ __half g_kh[QKV_EL];                        // [b,h,s,d] single
__device__ __half g_vth[QKV_EL];                       // [b,h,d,s] single
__device__ __half g_ch[MTOT * D_MODEL];                // ctx single

// ---------------- helpers ----------------------------------------------------
__device__ __forceinline__ unsigned pk(__half a, __half b) {
    return (unsigned)__half_as_ushort(a) | ((unsigned)__half_as_ushort(b) << 16);
}
__device__ __forceinline__ unsigned pkf(float a, float b) {
    return pk(__float2half_rn(a), __float2half_rn(b));
}
__device__ __forceinline__ void round_store4(float4 v, __half* hp) {
    *(uint2*)hp = make_uint2(pkf(v.x, v.y), pkf(v.z, v.w));
}
// fp32-accumulator mma (fp16 inputs)
__device__ __forceinline__ void mmaF(float* c, const unsigned* a, unsigned b0, unsigned b1) {
    asm volatile(
        "mma.sync.aligned.m16n8k16.row.col.f32.f16.f16.f32 "
        "{%0,%1,%2,%3}, {%4,%5,%6,%7}, {%8,%9}, {%0,%1,%2,%3};"
        : "+f"(c[0]), "+f"(c[1]), "+f"(c[2]), "+f"(c[3])
        : "r"(a[0]), "r"(a[1]), "r"(a[2]), "r"(a[3]), "r"(b0), "r"(b1));
}
__device__ __forceinline__ void ldsm4(unsigned r[4], const __half* p) {
    unsigned a = (unsigned)__cvta_generic_to_shared(p);
    asm volatile("ldmatrix.sync.aligned.m8n8.x4.shared.b16 {%0,%1,%2,%3}, [%4];"
                 : "=r"(r[0]), "=r"(r[1]), "=r"(r[2]), "=r"(r[3]) : "r"(a));
}
__device__ __forceinline__ void cp16(__half* s, const __half* g) {
    unsigned sa = (unsigned)__cvta_generic_to_shared(s);
    asm volatile("cp.async.cg.shared.global [%0], [%1], 16;" :: "r"(sa), "l"(g));
}
#define CP_COMMIT() asm volatile("cp.async.commit_group;")
#define CP_WAIT0()  asm volatile("cp.async.wait_group 0;")
#define CP_WAIT1()  asm volatile("cp.async.wait_group 1;")

// fast exp2 on the FMA pipe (MUFU-free)
__device__ __forceinline__ float exp2_fast(float y) {
    y = fmaxf(y, -120.f);
    float z = y + 12582912.f;
    int   e = __float_as_int(z);
    float f = y - (z - 12582912.f);
    float p = 1.f + f * (0.6931471805599453f + f * (0.2402265069591007f +
              f * (0.0555041086648216f + f * (0.0096181291076285f +
              f * 0.0013333558146429f))));
    return __int_as_float(__float_as_int(p) + (e << 23));
}
#define SCALE_LOG2E 0.18033688011112042f   // 0.125 * log2(e)

// ---------------- one-shot fp16 rounding of x + weights ----------------------
__global__ __launch_bounds__(256) void split_all(const float* __restrict__ x,
                                                 const float* __restrict__ Qw,
                                                 const float* __restrict__ Kw,
                                                 const float* __restrict__ Vw,
                                                 const float* __restrict__ Ow)
{
    const int idx = blockIdx.x * 256 + threadIdx.x;        // one float4 each
    if (idx < 2097152) {
        float4 v = ((const float4*)x)[idx];
        round_store4(v, g_xh + (size_t)idx * 4);
    } else {
        const int w = (idx - 2097152) >> 18;
        const size_t off = (size_t)((idx - 2097152) & 262143);
        const float* src = (w == 0) ? Qw : (w == 1) ? Kw : (w == 2) ? Vw : Ow;
        float4 v = ((const float4*)src)[off];
        round_store4(v, g_wh[w] + off * 4);
    }
}

// ---------------- 1-term fp16 GEMM: C = Ah @ Bh^T ----------------------------
// Block tile 128x128, BK=32, 128 threads = 4 warps (2m x 2n), warp tile 64x64.
#define SSTR 40
#define GBUF (128 * SSTR)
#define GSTG (2 * GBUF)               // Ah, Bh
#define GEMM_SMEM (2 * GSTG * 2)      // 40960 bytes

__device__ __forceinline__ void gemm_hf_body(const __half* __restrict__ Agh,
                                             const __half* __restrict__ Bgh,
                                             int m0, int n0,
                                             float (&c)[4][8][4],
                                             __half* sm)
{
    const int tid  = threadIdx.x;
    const int lane = tid & 31;
    const int warp = tid >> 5;
    const int wm   = (warp >> 1) * 64;
    const int wn   = (warp & 1) * 64;

    const int aoff = ((lane & 7) + ((lane >> 3) & 1) * 8) * SSTR + (lane >> 4) * 8;
    const int boff = ((lane & 7) + (lane >> 4) * 8) * SSTR + ((lane >> 3) & 1) * 8;

    int rowL[4], colL[4];
    #pragma unroll
    for (int u = 0; u < 4; u++) {
        const int idx = tid + 128 * u;
        rowL[u] = idx >> 2;
        colL[u] = (idx & 3) * 8;
    }

    {   // prologue: stage 0 <- k-tile 0
        __half* st = sm;
        #pragma unroll
        for (int u = 0; u < 4; u++) {
            const int so = rowL[u] * SSTR + colL[u];
            cp16(st + so,        Agh + (size_t)(m0 + rowL[u]) * D_MODEL + colL[u]);
            cp16(st + GBUF + so, Bgh + (size_t)(n0 + rowL[u]) * D_MODEL + colL[u]);
        }
        CP_COMMIT();
        CP_WAIT0();
    }
    __syncthreads();

    for (int kt = 0; kt < 32; kt++) {
        if (kt + 1 < 32) {
            __half* nx = sm + ((kt + 1) & 1) * GSTG;
            const int k0 = (kt + 1) * 32;
            #pragma unroll
            for (int u = 0; u < 4; u++) {
                const int so = rowL[u] * SSTR + colL[u];
                cp16(nx + so,        Agh + (size_t)(m0 + rowL[u]) * D_MODEL + k0 + colL[u]);
                cp16(nx + GBUF + so, Bgh + (size_t)(n0 + rowL[u]) * D_MODEL + k0 + colL[u]);
            }
            CP_COMMIT();
        }

        const __half* Ah = sm + (kt & 1) * GSTG;
        const __half* Bh = Ah + GBUF;

        #pragma unroll
        for (int ks = 0; ks < 2; ks++) {
            const int kk = ks * 16;
            unsigned a[4][4];
            #pragma unroll
            for (int i = 0; i < 4; i++)
                ldsm4(a[i], Ah + (wm + 16 * i) * SSTR + kk + aoff);
            #pragma unroll
            for (int p = 0; p < 4; p++) {
                unsigned bh[4];
                ldsm4(bh, Bh + (wn + 16 * p) * SSTR + kk + boff);
                const int j0 = 2 * p, j1 = j0 + 1;
                #pragma unroll
                for (int i = 0; i < 4; i++) {
                    mmaF(c[i][j0], a[i], bh[0], bh[1]);
                    mmaF(c[i][j1], a[i], bh[2], bh[3]);
                }
            }
        }
        CP_WAIT0();
        __syncthreads();
    }
}

// Fused QKV projection; blockIdx.z selects weight. All 1-term.
__global__ __launch_bounds__(128, 2) void gemm_qkv()
{
    extern __shared__ __half smg[];
    float c[4][8][4];
    #pragma unroll
    for (int i = 0; i < 4; i++)
        #pragma unroll
        for (int j = 0; j < 8; j++)
            #pragma unroll
            for (int q = 0; q < 4; q++) c[i][j][q] = 0.f;

    const int m0 = blockIdx.y * 128;
    const int n0 = blockIdx.x * 128;
    const int z  = blockIdx.z;

    gemm_hf_body(g_xh, g_wh[z], m0, n0, c, smg);

    const int tid  = threadIdx.x;
    const int lane = tid & 31;
    const int g = lane >> 2, t = lane & 3;
    const int warp = tid >> 5;
    const int wm = (warp >> 1) * 64, wn = (warp & 1) * 64;

    if (z == 2) {
        #define VS 136
        __half* vs = smg;
        __syncthreads();
        #pragma unroll
        for (int i = 0; i < 4; i++) {
            #pragma unroll
            for (int j = 0; j < 8; j++) {
                const int nn = wn + 8 * j + 2 * t;
                const int mm = wm + 16 * i + g;
                vs[(nn    ) * VS + mm    ] = __float2half_rn(c[i][j][0]);
                vs[(nn + 1) * VS + mm    ] = __float2half_rn(c[i][j][1]);
                vs[(nn    ) * VS + mm + 8] = __float2half_rn(c[i][j][2]);
                vs[(nn + 1) * VS + mm + 8] = __float2half_rn(c[i][j][3]);
            }
        }
        __syncthreads();
        const int r = tid;
        const int n = n0 + r;
        const int h = n >> 6, d = n & 63;
        const int b = m0 >> 11, s0 = m0 & 2047;
        __half* dst = g_vth + ((size_t)(b * NUM_HEADS + h) * D_HEAD + d) * SEQ + s0;
        const __half* src = vs + r * VS;
        #pragma unroll
        for (int u = 0; u < 16; u++)
            *(uint4*)&dst[8 * u] = *(const uint4*)&src[8 * u];
        #undef VS
    } else {
        __half* dst = (z == 0) ? g_qh : g_kh;
        #pragma unroll
        for (int i = 0; i < 4; i++) {
            #pragma unroll
            for (int j = 0; j < 8; j++) {
                const int n = n0 + wn + 8 * j + 2 * t;
                const int h = n >> 6, d = n & 63;
                const int r0 = m0 + wm + 16 * i + g;
                const int r1 = r0 + 8;
                const int b0 = r0 >> 11, s0 = r0 & 2047;
                const int b1 = r1 >> 11, s1 = r1 & 2047;
                const size_t i0 = ((size_t)(b0 * NUM_HEADS + h) * SEQ + s0) * D_HEAD + d;
                const size_t i1 = ((size_t)(b1 * NUM_HEADS + h) * SEQ + s1) * D_HEAD + d;
                *(unsigned*)&dst[i0] = pkf(c[i][j][0], c[i][j][1]);
                *(unsigned*)&dst[i1] = pkf(c[i][j][2], c[i][j][3]);
            }
        }
    }
}

// Output projection: out = ctx @ Ow^T, fp32 out. 1-term GEMM.
__global__ __launch_bounds__(128, 2) void gemm_out(float* __restrict__ out)
{
    extern __shared__ __half smg[];
    float c[4][8][4];
    #pragma unroll
    for (int i = 0; i < 4; i++)
        #pragma unroll
        for (int j = 0; j < 8; j++)
            #pragma unroll
            for (int q = 0; q < 4; q++) c[i][j][q] = 0.f;

    const int m0 = blockIdx.y * 128;
    const int n0 = blockIdx.x * 128;

    gemm_hf_body(g_ch, g_wh[3], m0, n0, c, smg);

    const int lane = threadIdx.x & 31;
    const int g = lane >> 2, t = lane & 3;
    const int warp = threadIdx.x >> 5;
    const int wm = (warp >> 1) * 64, wn = (warp & 1) * 64;

    #pragma unroll
    for (int i = 0; i < 4; i++) {
        #pragma unroll
        for (int j = 0; j < 8; j++) {
            const int n  = n0 + wn + 8 * j + 2 * t;
            const int r0 = m0 + wm + 16 * i + g;
            *(float2*)&out[(size_t)r0 * D_MODEL + n] = make_float2(c[i][j][0], c[i][j][1]);
            *(float2*)&out[(size_t)(r0 + 8) * D_MODEL + n] = make_float2(c[i][j][2], c[i][j][3]);
        }
    }
}

// ---------------- Flash attention (R14 shape) + register-direct P ------------
// Block = (b, h, 128-q-tile). 256 threads = 8 warps, warp strip 16 rows.
// P never touches smem: the S C-fragment IS the PV A-fragment layout.
#define QSTR 72
#define TILEC (64 * QSTR)
#define ATTN_SMEM (4 * TILEC * 2)         // 36864 bytes: 2 KV stages only

__global__ __launch_bounds__(256, 2) void attn_mma(const unsigned char* __restrict__ pm)
{
    extern __shared__ __half smb[];
    __half* stg0 = smb;                   // {Kh, Vth} stage 0
    __half* stg1 = smb + 2 * TILEC;       // stage 1

    const int qt = gridDim.x - 1 - blockIdx.x;   // heavy blocks first
    const int h  = blockIdx.y;
    const int b  = blockIdx.z;
    const int tid  = threadIdx.x;
    const int lane = tid & 31;
    const int warp = tid >> 5;
    const int g = lane >> 2, t = lane & 3;
    const size_t base = (size_t)(b * NUM_HEADS + h) * SEQ;

    const int rw = warp * 16;
    const int Rg = qt * 128 + rw;
    const int kt_max = 2 * qt + 1;

    const int aoffQ = ((lane & 7) + ((lane >> 3) & 1) * 8) * QSTR + (lane >> 4) * 8;
    const int boffQ = ((lane & 7) + (lane >> 4) * 8) * QSTR + ((lane >> 3) & 1) * 8;

    const int krow = tid >> 2;
    const int kcs  = (tid & 3) * 16;
    const int kso  = krow * QSTR + kcs;
    const size_t vbase = ((size_t)(b * NUM_HEADS + h) * D_HEAD + krow) * SEQ + kcs;
    const size_t kbase = (base + krow) * D_HEAD + kcs;

    // ---- stage Q single into smb[0..2T), move to regs ----
    {
        const int row = tid >> 1, cs = (tid & 1) * 32;
        const size_t ga = (base + (size_t)qt * 128 + row) * D_HEAD + cs;
        const int so = row * QSTR + cs;
        #pragma unroll
        for (int u = 0; u < 4; u++)
            cp16(&smb[so + 8 * u], &g_qh[ga + 8 * u]);
        CP_COMMIT();
        CP_WAIT0();
    }
    __syncthreads();

    unsigned qh[4][4];
    #pragma unroll
    for (int ks = 0; ks < 4; ks++)
        ldsm4(qh[ks], smb + rw * QSTR + 16 * ks + aoffQ);
    __syncthreads();                      // smem free for KV stages

    // ---- prologue: KV(0) into stg0 ----
    {
        cp16(&stg0[kso],         &g_kh[kbase]);  cp16(&stg0[kso + 8],         &g_kh[kbase + 8]);
        cp16(&stg0[TILEC + kso], &g_vth[vbase]); cp16(&stg0[TILEC + kso + 8], &g_vth[vbase + 8]);
        CP_COMMIT();
    }

    float o[8][4];
    float m_i[2] = {-1e30f, -1e30f};
    float l_i[2] = {0.f, 0.f};
    #pragma unroll
    for (int j = 0; j < 8; j++)
        #pragma unroll
        for (int q = 0; q < 4; q++) o[j][q] = 0.f;

    for (int kt = 0; kt <= kt_max; kt++) {
        if (kt < kt_max) {
            __half* nx = ((kt + 1) & 1) ? stg1 : stg0;
            const size_t gk = kbase + (size_t)(kt + 1) * 64 * D_HEAD;
            const size_t gv = vbase + (size_t)(kt + 1) * 64;
            cp16(&nx[kso],         &g_kh[gk]);  cp16(&nx[kso + 8],         &g_kh[gk + 8]);
            cp16(&nx[TILEC + kso], &g_vth[gv]); cp16(&nx[TILEC + kso + 8], &g_vth[gv + 8]);
            CP_COMMIT();
            CP_WAIT1();                    // KV(kt) complete
        } else {
            CP_WAIT0();
        }
        __syncthreads();

        const int C0 = kt * 64;
        if (C0 <= Rg + 15) {
            const __half* Kh = (kt & 1) ? stg1 : stg0;
            const __half* Vh = Kh + TILEC;

            float s[8][4];
            #pragma unroll
            for (int j = 0; j < 8; j++)
                #pragma unroll
                for (int q = 0; q < 4; q++) s[j][q] = 0.f;

            // ---- S = Q @ Kh^T (1-term) ----
            #pragma unroll
            for (int ks = 0; ks < 4; ks++) {
                const int kk = 16 * ks;
                #pragma unroll
                for (int p = 0; p < 2; p++) {
                    unsigned bh0[4], bh1[4];
                    ldsm4(bh0, Kh + (32 * p     ) * QSTR + kk + boffQ);
                    ldsm4(bh1, Kh + (32 * p + 16) * QSTR + kk + boffQ);
                    const int j0 = 4 * p;
                    mmaF(s[j0 + 0], qh[ks], bh0[0], bh0[1]);
                    mmaF(s[j0 + 1], qh[ks], bh0[2], bh0[3]);
                    mmaF(s[j0 + 2], qh[ks], bh1[0], bh1[1]);
                    mmaF(s[j0 + 3], qh[ks], bh1[2], bh1[3]);
                }
            }

            // ---- scale (log2 domain) + causal + padding masks ----
            const unsigned char* pmb = pm + (size_t)b * SEQ + C0;
            const int r0 = Rg + g, r1 = r0 + 8;
            #pragma unroll
            for (int j = 0; j < 8; j++) {
                const int c0 = C0 + 8 * j + 2 * t, c1 = c0 + 1;
                const bool p0 = pmb[8 * j + 2 * t] != 0;
                const bool p1 = pmb[8 * j + 2 * t + 1] != 0;
                float v;
                v = s[j][0] * SCALE_LOG2E; if (c0 > r0 || p0) v = -1e30f; s[j][0] = v;
                v = s[j][1] * SCALE_LOG2E; if (c1 > r0 || p1) v = -1e30f; s[j][1] = v;
                v = s[j][2] * SCALE_LOG2E; if (c0 > r1 || p0) v = -1e30f; s[j][2] = v;
                v = s[j][3] * SCALE_LOG2E; if (c1 > r1 || p1) v = -1e30f; s[j][3] = v;
            }

            // ---- online softmax, base-2, FMA-pipe exp ----
            #pragma unroll
            for (int rr = 0; rr < 2; rr++) {
                float rm = -1e30f;
                #pragma unroll
                for (int j = 0; j < 8; j++)
                    rm = fmaxf(rm, fmaxf(s[j][2 * rr], s[j][2 * rr + 1]));
                rm = fmaxf(rm, __shfl_xor_sync(0xffffffffu, rm, 1));
                rm = fmaxf(rm, __shfl_xor_sync(0xffffffffu, rm, 2));
                const float mn    = fmaxf(m_i[rr], rm);
                const float alpha = exp2_fast(m_i[rr] - mn);
                m_i[rr] = mn;
                float rs = 0.f;
                #pragma unroll
                for (int j = 0; j < 8; j++) {
                    s[j][2 * rr    ] = exp2_fast(s[j][2 * rr    ] - mn);
                    s[j][2 * rr + 1] = exp2_fast(s[j][2 * rr + 1] - mn);
                    rs += s[j][2 * rr] + s[j][2 * rr + 1];
                }
                rs += __shfl_xor_sync(0xffffffffu, rs, 1);
                rs += __shfl_xor_sync(0xffffffffu, rs, 2);
                l_i[rr] = l_i[rr] * alpha + rs;
                #pragma unroll
                for (int j = 0; j < 8; j++) {
                    o[j][2 * rr    ] *= alpha;
                    o[j][2 * rr + 1] *= alpha;
                }
            }

            // ---- O += P @ Vh: P built in-register from S C-fragments ----
            // C-frag (rows g/g+8, cols 8j+2t) == A-frag (rows g/g+8, k=16ks+2t):
            //   a0 = s[2ks][0:1], a1 = s[2ks][2:3], a2 = s[2ks+1][0:1], a3 = s[2ks+1][2:3]
            #pragma unroll
            for (int ks = 0; ks < 4; ks++) {
                const int kk = 16 * ks;
                unsigned ph[4];
                ph[0] = pkf(s[2 * ks    ][0], s[2 * ks    ][1]);
                ph[1] = pkf(s[2 * ks    ][2], s[2 * ks    ][3]);
                ph[2] = pkf(s[2 * ks + 1][0], s[2 * ks + 1][1]);
                ph[3] = pkf(s[2 * ks + 1][2], s[2 * ks + 1][3]);
                #pragma unroll
                for (int p = 0; p < 2; p++) {
                    unsigned bh0[4], bh1[4];
                    ldsm4(bh0, Vh + (32 * p     ) * QSTR + kk + boffQ);
                    ldsm4(bh1, Vh + (32 * p + 16) * QSTR + kk + boffQ);
                    const int j0 = 4 * p;
                    mmaF(o[j0 + 0], ph, bh0[0], bh0[1]);
                    mmaF(o[j0 + 1], ph, bh0[2], bh0[3]);
                    mmaF(o[j0 + 2], ph, bh1[0], bh1[1]);
                    mmaF(o[j0 + 3], ph, bh1[2], bh1[3]);
                }
            }
        }
        __syncthreads();
    }

    // ---- normalize + write ctx single [b, s, h*64 + col] ----
    const float inv0 = 1.f / l_i[0];
    const float inv1 = 1.f / l_i[1];
    const int row0 = qt * 128 + rw + g;
    const size_t d0 = ((size_t)b * SEQ + row0    ) * D_MODEL + h * D_HEAD;
    const size_t d1 = ((size_t)b * SEQ + row0 + 8) * D_MODEL + h * D_HEAD;
    #pragma unroll
    for (int j = 0; j < 8; j++) {
        const int cidx = 8 * j + 2 * t;
        *(unsigned*)&g_ch[d0 + cidx] = pkf(o[j][0] * inv0, o[j][1] * inv0);
        *(unsigned*)&g_ch[d1 + cidx] = pkf(o[j][2] * inv1, o[j][3] * inv1);
    }
}

// ---------------- launch ----------------------------------------------------
extern "C" void kernel_launch(void* const* d_in, const int* in_sizes, int n_in,
                              void* d_out, int out_size)
{
    (void)in_sizes; (void)n_in; (void)out_size;
    const float* x  = (const float*)d_in[0];
    const float* Qw = (const float*)d_in[1];
    const float* Kw = (const float*)d_in[2];
    const float* Vw = (const float*)d_in[3];
    const float* Ow = (const float*)d_in[4];
    const unsigned char* pm = (const unsigned char*)d_in[5];
    float* out = (float*)d_out;

    cudaFuncSetAttribute(attn_mma, cudaFuncAttributeMaxDynamicSharedMemorySize, ATTN_SMEM);
    cudaFuncSetAttribute(gemm_qkv, cudaFuncAttributeMaxDynamicSharedMemorySize, GEMM_SMEM);
    cudaFuncSetAttribute(gemm_out, cudaFuncAttributeMaxDynamicSharedMemorySize, GEMM_SMEM);

    split_all<<<12288, 256>>>(x, Qw, Kw, Vw, Ow);

    dim3 gq(D_MODEL / 128, MTOT / 128, 3);        // 8 x 64 x 3
    gemm_qkv<<<gq, 128, GEMM_SMEM>>>();

    dim3 ga(SEQ / 128, NUM_HEADS, BATCH);         // 16 x 16 x 4
    attn_mma<<<ga, 256, ATTN_SMEM>>>(pm);

    dim3 go(D_MODEL / 128, MTOT / 128);           // 8 x 64
    gemm_out<<<go, 128, GEMM_SMEM>>>(out);
}